// round 16
// baseline (speedup 1.0000x reference)
#include <cuda_runtime.h>
#include <cuda_bf16.h>
#include <cstdint>
#include <math.h>

// Problem constants
#define BATCH  4
#define S_LEN  2048
#define NHEAD  12
#define DHEAD  100
#define HIDDEN 1200
#define M_TOT  (BATCH * S_LEN)          // 8192
#define BH     (BATCH * NHEAD)          // 48
#define PCOLS  1216                     // K padded (19*64)
#define PU32   608                      // PCOLS/2 in u32
#define PROWSW 1280                     // weight rows padded

// ---------------------------------------------------------------------------
// Scratch (pre-split bf16 hi/lo, SEPARATE arrays — known-good layout)
// ---------------------------------------------------------------------------
__device__ __align__(16) __nv_bfloat16 g_xhi[M_TOT * PCOLS];
__device__ __align__(16) __nv_bfloat16 g_xlo[M_TOT * PCOLS];
__device__ __align__(16) __nv_bfloat16 g_whi[4][PROWSW * PCOLS];
__device__ __align__(16) __nv_bfloat16 g_wlo[4][PROWSW * PCOLS];
// Q,K: (bh, s, 52 u32) packed bf16 pairs along d (pads 50,51 zero)
__device__ __align__(16) unsigned g_qhi[BH * S_LEN * 52];
__device__ __align__(16) unsigned g_qlo[BH * S_LEN * 52];
__device__ __align__(16) unsigned g_khi[BH * S_LEN * 52];
__device__ __align__(16) unsigned g_klo[BH * S_LEN * 52];
// V^T: (bh, 104 d-rows, 1024 u32) packed pairs along s (d rows 100..103 zero)
__device__ __align__(16) unsigned g_vthi[BH * 104 * 1024];
__device__ __align__(16) unsigned g_vtlo[BH * 104 * 1024];
// O: padded (8192, 608 u32) packed pairs (cols 600..607 zero)
__device__ __align__(16) unsigned g_ohi[M_TOT * PU32];
__device__ __align__(16) unsigned g_olo[M_TOT * PU32];

// ---------------------------------------------------------------------------
// BF16 helpers + mma.sync + ldmatrix + cp.async
// ---------------------------------------------------------------------------
__device__ __forceinline__ unsigned cvt2(float even, float odd) {
    unsigned r;
    asm("cvt.rn.bf16x2.f32 %0, %1, %2;" : "=r"(r) : "f"(odd), "f"(even));
    return r;
}
__device__ __forceinline__ float bf_lo(unsigned p) { return __uint_as_float(p << 16); }
__device__ __forceinline__ float bf_hi(unsigned p) { return __uint_as_float(p & 0xFFFF0000u); }
__device__ __forceinline__ void split2(float e, float o, unsigned& h, unsigned& l) {
    h = cvt2(e, o);
    l = cvt2(e - bf_lo(h), o - bf_hi(h));
}
__device__ __forceinline__ void mma16(float* c, const unsigned* a, const unsigned* b) {
    asm volatile(
        "mma.sync.aligned.m16n8k16.row.col.f32.bf16.bf16.f32 "
        "{%0,%1,%2,%3}, {%4,%5,%6,%7}, {%8,%9}, {%0,%1,%2,%3};\n"
        : "+f"(c[0]), "+f"(c[1]), "+f"(c[2]), "+f"(c[3])
        : "r"(a[0]), "r"(a[1]), "r"(a[2]), "r"(a[3]), "r"(b[0]), "r"(b[1]));
}
__device__ __forceinline__ void mma8b(float* c, const unsigned* a, unsigned b) {
    asm volatile(
        "mma.sync.aligned.m16n8k8.row.col.f32.bf16.bf16.f32 "
        "{%0,%1,%2,%3}, {%4,%5}, {%6}, {%0,%1,%2,%3};\n"
        : "+f"(c[0]), "+f"(c[1]), "+f"(c[2]), "+f"(c[3])
        : "r"(a[0]), "r"(a[1]), "r"(b));
}
__device__ __forceinline__ void ldsm_x4(unsigned& r0, unsigned& r1, unsigned& r2,
                                        unsigned& r3, uint32_t a) {
    asm volatile("ldmatrix.sync.aligned.m8n8.x4.shared.b16 {%0,%1,%2,%3}, [%4];"
                 : "=r"(r0), "=r"(r1), "=r"(r2), "=r"(r3) : "r"(a));
}
__device__ __forceinline__ void ldsm_x2(unsigned& r0, unsigned& r1, uint32_t a) {
    asm volatile("ldmatrix.sync.aligned.m8n8.x2.shared.b16 {%0,%1}, [%2];"
                 : "=r"(r0), "=r"(r1) : "r"(a));
}
__device__ __forceinline__ void cpa16(uint32_t s_addr, const void* g) {
    asm volatile("cp.async.cg.shared.global [%0], [%1], 16;" :: "r"(s_addr), "l"(g));
}
__device__ __forceinline__ void cpa_commit() {
    asm volatile("cp.async.commit_group;");
}
__device__ __forceinline__ void cpa_wait0() {
    asm volatile("cp.async.wait_group 0;");
}
__device__ __forceinline__ uint32_t smem_u32p(const void* p) {
    uint32_t a;
    asm("{ .reg .u64 t; cvta.to.shared.u64 t, %1; cvt.u32.u64 %0, t; }" : "=r"(a) : "l"(p));
    return a;
}

// ---------------------------------------------------------------------------
// Prep: fp32 -> bf16 hi/lo for x AND all 4 weights in ONE launch.
// ---------------------------------------------------------------------------
__global__ void split_all_kernel(const float* __restrict__ x,
                                 const float* __restrict__ w0, const float* __restrict__ w1,
                                 const float* __restrict__ w2, const float* __restrict__ w3,
                                 __nv_bfloat16* __restrict__ xhi, __nv_bfloat16* __restrict__ xlo,
                                 __nv_bfloat16* __restrict__ whi, __nv_bfloat16* __restrict__ wlo)
{
    const long totX = (long)M_TOT * PCOLS;
    const long totW = (long)PROWSW * PCOLS;
    const long i = (long)blockIdx.x * 256 + threadIdx.x;
    if (i >= totX + 4 * totW) return;

    const float* src;
    __nv_bfloat16 *dhi, *dlo;
    int rows;
    long j;
    if (i < totX) {
        src = x; dhi = xhi; dlo = xlo; rows = M_TOT; j = i;
    } else {
        const long t = i - totX;
        const int wsel = (int)(t / totW);
        j = t - (long)wsel * totW;
        src = (wsel == 0) ? w0 : (wsel == 1) ? w1 : (wsel == 2) ? w2 : w3;
        dhi = whi + (long)wsel * totW;
        dlo = wlo + (long)wsel * totW;
        rows = HIDDEN;
    }
    const int r = (int)(j / PCOLS);
    const int c = (int)(j - (long)r * PCOLS);
    float v = (r < rows && c < HIDDEN) ? src[(long)r * HIDDEN + c] : 0.f;
    __nv_bfloat16 h = __float2bfloat16(v);
    dhi[j] = h;
    dlo[j] = __float2bfloat16(v - __bfloat162float(h));
}

// Zero pads (Q/K cols 50,51; Vt d-rows 100..103; O cols 600..607) AND zero
// the fp32 output buffer (required: gemm_o accumulates via atomicAdd).
__global__ void init_pads_kernel(unsigned* qhi, unsigned* qlo, unsigned* khi, unsigned* klo,
                                 unsigned* vthi, unsigned* vtlo, unsigned* ohi, unsigned* olo,
                                 float* out)
{
    const long i = (long)blockIdx.x * 256 + threadIdx.x;
    if (i < (long)M_TOT * HIDDEN) out[i] = 0.f;
    if (i < BH * S_LEN * 2) {
        const long r = i >> 1;
        const long a = r * 52 + 50 + (i & 1);
        qhi[a] = 0u; qlo[a] = 0u; khi[a] = 0u; klo[a] = 0u;
    }
    if (i < BH * 4 * 1024) {
        const long bh = i >> 12;
        const long a = (bh * 104 + 100) * 1024 + (i & 4095);
        vthi[a] = 0u; vtlo[a] = 0u;
    }
    if (i < M_TOT * 8) {
        const long a = (i >> 3) * PU32 + 600 + (i & 7);
        ohi[a] = 0u; olo[a] = 0u;
    }
}

// ---------------------------------------------------------------------------
// GEMM core (R12/R15 known-good shape): C[m,n] = sum_{k in [ch0,ch1)} ...
// 128x128 tile, BK=64, 256 threads, warp tile 64x32, 2 CTAs/SM.
// smem u32 arrays [128][36]: AHI ALO BHI BLO.  cp.async + immediate wait.
// mode 0: f32 atomicAdd (M,1200);  mode 1: Q/K hi-lo layout;  mode 3: V^T.
// ---------------------------------------------------------------------------
#define GS_ALO 18432
#define GS_BHI 36864
#define GS_BLO 55296
#define GT_SMEM 73728

__device__ __forceinline__ void gemm_core(
    unsigned char* smb,
    const unsigned* __restrict__ Ahi_u, const unsigned* __restrict__ Alo_u,
    const unsigned* __restrict__ Bhi_u, const unsigned* __restrict__ Blo_u,
    float* __restrict__ Cf, unsigned* __restrict__ Chi, unsigned* __restrict__ Clo,
    int mode, int m0, int n0, int ch0, int ch1)
{
    unsigned* AHI = (unsigned*)smb;
    unsigned* ALO = (unsigned*)(smb + GS_ALO);
    unsigned* BHI = (unsigned*)(smb + GS_BHI);
    unsigned* BLO = (unsigned*)(smb + GS_BLO);
    const uint32_t sb = smem_u32p(smb);

    const int tid  = threadIdx.x;
    const int lane = tid & 31;
    const int warp = tid >> 5;
    const int wm   = warp >> 2;     // 0..1
    const int wn   = warp & 3;      // 0..3
    const int lr   = lane >> 2;
    const int lc   = lane & 3;

    float acc[4][4][4];
#pragma unroll
    for (int i = 0; i < 4; i++)
#pragma unroll
        for (int j = 0; j < 4; j++)
#pragma unroll
            for (int r = 0; r < 4; r++) acc[i][j][r] = 0.f;

    const int lrow = tid >> 3;        // 0..31
    const int cn   = tid & 7;         // 16B chunk

    for (int ch = ch0; ch < ch1; ch++) {
        __syncthreads();
#pragma unroll
        for (int q = 0; q < 4; q++) {
            const int row = lrow + q * 32;
            const long a_off = (long)(m0 + row) * PU32 + ch * 32 + cn * 4;
            const long b_off = (long)(n0 + row) * PU32 + ch * 32 + cn * 4;
            const uint32_t so = (uint32_t)(row * 36 + cn * 4) * 4;
            cpa16(sb + so,          Ahi_u + a_off);
            cpa16(sb + GS_ALO + so, Alo_u + a_off);
            cpa16(sb + GS_BHI + so, Bhi_u + b_off);
            cpa16(sb + GS_BLO + so, Blo_u + b_off);
        }
        cpa_commit();
        cpa_wait0();
        __syncthreads();

#pragma unroll
        for (int s = 0; s < 4; s++) {
            unsigned bhv[4][2], blv[4][2];
#pragma unroll
            for (int nt = 0; nt < 4; nt++) {
                const int n = wn * 32 + nt * 8 + lr;
                bhv[nt][0] = BHI[n * 36 + 8 * s + lc];
                bhv[nt][1] = BHI[n * 36 + 8 * s + 4 + lc];
                blv[nt][0] = BLO[n * 36 + 8 * s + lc];
                blv[nt][1] = BLO[n * 36 + 8 * s + 4 + lc];
            }
#pragma unroll
            for (int mt = 0; mt < 4; mt++) {
                const int m = wm * 64 + mt * 16 + lr;
                unsigned ah[4], al[4];
                ah[0] = AHI[m * 36 + 8 * s + lc];       ah[1] = AHI[(m + 8) * 36 + 8 * s + lc];
                ah[2] = AHI[m * 36 + 8 * s + 4 + lc];   ah[3] = AHI[(m + 8) * 36 + 8 * s + 4 + lc];
                al[0] = ALO[m * 36 + 8 * s + lc];       al[1] = ALO[(m + 8) * 36 + 8 * s + lc];
                al[2] = ALO[m * 36 + 8 * s + 4 + lc];   al[3] = ALO[(m + 8) * 36 + 8 * s + 4 + lc];
#pragma unroll
                for (int nt = 0; nt < 4; nt++) {
                    mma16(acc[mt][nt], ah, bhv[nt]);
                    mma16(acc[mt][nt], ah, blv[nt]);
                    mma16(acc[mt][nt], al, bhv[nt]);
                }
            }
        }
    }

    // ---- Epilogue ----
    if (mode == 3) {
        __syncthreads();
        float* Ct = (float*)smb;   // [128 n][129 m]
#pragma unroll
        for (int mt = 0; mt < 4; mt++)
#pragma unroll
            for (int nt = 0; nt < 4; nt++) {
                const int mL = wm * 64 + mt * 16 + lr;
                const int nL = wn * 32 + nt * 8 + lc * 2;
                Ct[(nL)     * 129 + mL]     = acc[mt][nt][0];
                Ct[(nL + 1) * 129 + mL]     = acc[mt][nt][1];
                Ct[(nL)     * 129 + mL + 8] = acc[mt][nt][2];
                Ct[(nL + 1) * 129 + mL + 8] = acc[mt][nt][3];
            }
        __syncthreads();
#pragma unroll
        for (int it = 0; it < 32; it++) {
            const int idx = tid + it * 256;    // 0..8191
            const int nL  = idx >> 6;          // 0..127
            const int mp  = idx & 63;          // m-pair
            const int n   = n0 + nL;
            if (n < HIDDEN) {
                const float c0 = Ct[nL * 129 + 2 * mp];
                const float c1 = Ct[nL * 129 + 2 * mp + 1];
                const int m = m0 + 2 * mp;
                const int b_ = m >> 11, s_ = m & (S_LEN - 1);
                const int h_ = n / DHEAD, d_ = n % DHEAD;
                unsigned h, l;
                split2(c0, c1, h, l);
                const long a = ((long)(b_ * NHEAD + h_) * 104 + d_) * 1024 + (s_ >> 1);
                Chi[a] = h; Clo[a] = l;
            }
        }
        return;
    }

#pragma unroll
    for (int mt = 0; mt < 4; mt++) {
#pragma unroll
        for (int nt = 0; nt < 4; nt++) {
            const int nn = n0 + wn * 32 + nt * 8 + lc * 2;
            if (nn >= HIDDEN) continue;
#pragma unroll
            for (int half = 0; half < 2; half++) {
                const int mm = m0 + wm * 64 + mt * 16 + lr + half * 8;
                const float c0 = acc[mt][nt][half * 2];
                const float c1 = acc[mt][nt][half * 2 + 1];
                if (mode == 0) {
                    atomicAdd(&Cf[(long)mm * HIDDEN + nn],     c0);
                    atomicAdd(&Cf[(long)mm * HIDDEN + nn + 1], c1);
                } else {
                    const int b_ = mm >> 11, s_ = mm & (S_LEN - 1);
                    const int h_ = nn / DHEAD, d_ = nn % DHEAD;
                    unsigned h, l;
                    split2(c0, c1, h, l);
                    const long a = ((long)(b_ * NHEAD + h_) * S_LEN + s_) * 52 + (d_ >> 1);
                    Chi[a] = h; Clo[a] = l;
                }
            }
        }
    }
}

// Fused QKV: grid.z selects weight + destination + mode.  Full K range.
__global__ __launch_bounds__(256, 2) void gemm_qkv_kernel(
    const __nv_bfloat16* __restrict__ xhi, const __nv_bfloat16* __restrict__ xlo,
    const __nv_bfloat16* __restrict__ whi, const __nv_bfloat16* __restrict__ wlo,
    unsigned* __restrict__ qhi, unsigned* __restrict__ qlo,
    unsigned* __restrict__ khi, unsigned* __restrict__ klo,
    unsigned* __restrict__ vthi, unsigned* __restrict__ vtlo)
{
    extern __shared__ unsigned char smb[];
    const int z = blockIdx.z;
    const long wo = (long)z * PROWSW * PCOLS;
    unsigned* Chi = (z == 0) ? qhi : (z == 1) ? khi : vthi;
    unsigned* Clo = (z == 0) ? qlo : (z == 1) ? klo : vtlo;
    const int mode = (z == 2) ? 3 : 1;
    gemm_core(smb,
              (const unsigned*)xhi, (const unsigned*)xlo,
              (const unsigned*)(whi + wo), (const unsigned*)(wlo + wo),
              nullptr, Chi, Clo, mode,
              blockIdx.x * 128, blockIdx.y * 128, 0, PCOLS / 64);
}

// Output projection with split-K=2: grid.z picks k-chunk range; partial sums
// accumulate into pre-zeroed fp32 out via atomicAdd (deterministic: x+y).
__global__ __launch_bounds__(256, 2) void gemm_o_kernel(
    const unsigned* __restrict__ ohi, const unsigned* __restrict__ olo,
    const __nv_bfloat16* __restrict__ whi, const __nv_bfloat16* __restrict__ wlo,
    float* __restrict__ out)
{
    extern __shared__ unsigned char smb[];
    const int kz  = blockIdx.z;                    // 0 or 1
    const int ch0 = (kz == 0) ? 0 : 10;
    const int ch1 = (kz == 0) ? 10 : PCOLS / 64;   // 19
    gemm_core(smb, ohi, olo,
              (const unsigned*)whi, (const unsigned*)wlo,
              out, nullptr, nullptr, 0,
              blockIdx.x * 128, blockIdx.y * 128, ch0, ch1);
}

// ---------------------------------------------------------------------------
// Flash attention (R15 verbatim: bf16 3-mma, ldmatrix frags, cp.async loads,
// exp2-domain softmax). 256 threads, q-tile 128, kv 64.
// ---------------------------------------------------------------------------
#define QST 52
#define VTS 36
#define QHI_OFF  0
#define QLO_OFF  6656
#define KHI_OFF  13312
#define KLO_OFF  16640
#define VTHI_OFF 19968
#define VTLO_OFF 23712
#define BIAS_OFF 27456
#define FL_SMEM_U32 27520
#define FL_SMEM_BYTES (FL_SMEM_U32 * 4)
#define NDT 13

__global__ __launch_bounds__(256, 2) void flash_kernel(
    const float* __restrict__ alibi, const float* __restrict__ mask,
    const int* __restrict__ layer_index,
    const unsigned* __restrict__ qhi_g, const unsigned* __restrict__ qlo_g,
    const unsigned* __restrict__ khi_g, const unsigned* __restrict__ klo_g,
    const unsigned* __restrict__ vthi_g, const unsigned* __restrict__ vtlo_g,
    unsigned* __restrict__ ohi_g, unsigned* __restrict__ olo_g)
{
    extern __shared__ unsigned smu[];
    unsigned* Qhi  = smu + QHI_OFF;
    unsigned* Qlo  = smu + QLO_OFF;
    float*    bias = (float*)(smu + BIAS_OFF);

    const int tid  = threadIdx.x;
    const int lane = tid & 31;
    const int w    = tid >> 5;
    const int lr   = lane >> 2;
    const int lc   = lane & 3;
    const int bh   = blockIdx.x;
    const int q0   = blockIdx.y * 128;
    const int b_   = bh / NHEAD;
    const int h_   = bh % NHEAD;

    const float LOG2E = 1.4426950408889634f;
    const float inv = 1.f / (float)(layer_index[0] + 1);
    const float sc  = 10.f * inv * LOG2E;
    const float bsc = inv * LOG2E;

    const int g8 = lane >> 3;
    const int r8 = lane & 7;
    const int gh = (lane >> 3) & 1;

    const uint32_t qhiB = smem_u32p(smu + QHI_OFF), qloB = smem_u32p(smu + QLO_OFF);
    const uint32_t khiB = smem_u32p(smu + KHI_OFF), kloB = smem_u32p(smu + KLO_OFF);
    const uint32_t vhiB = smem_u32p(smu + VTHI_OFF), vloB = smem_u32p(smu + VTLO_OFF);

    const int q_row = 16 * w + ((g8 & 1) << 3) + r8;
    const uint32_t q_off0 = (uint32_t)(q_row * QST + ((g8 >> 1) << 2)) * 4;
    const int kv_rowoff = ((g8 >> 1) << 3) + r8;
    const int kv_coloff = (g8 & 1) << 2;

    {
        const long qbase = ((long)bh * S_LEN + q0) * 52;
        for (int id = tid; id < 128 * 13; id += 256) {
            const int r  = id / 13;
            const int c4 = (id % 13) * 4;
            *(uint4*)&Qhi[r * QST + c4] = *(const uint4*)&qhi_g[qbase + r * 52 + c4];
            *(uint4*)&Qlo[r * QST + c4] = *(const uint4*)&qlo_g[qbase + r * 52 + c4];
        }
    }

    float oacc[NDT][4];
#pragma unroll
    for (int nt = 0; nt < NDT; nt++)
#pragma unroll
        for (int r = 0; r < 4; r++) oacc[nt][r] = 0.f;
    float mrow0 = -1e30f, mrow1 = -1e30f, lsum0 = 0.f, lsum1 = 0.f;

    const int ar = 16 * w + lr;

    for (int kt = 0; kt < S_LEN / 64; kt++) {
        const int k0g = kt * 64;
        __syncthreads();

        {
            const long kbase = ((long)bh * S_LEN + k0g) * 52;
            for (int id = tid; id < 64 * 13; id += 256) {
                const int r  = id / 13;
                const int c4 = (id % 13) * 4;
                const uint32_t so = (uint32_t)(r * QST + c4) * 4;
                cpa16(khiB + so, khi_g + kbase + r * 52 + c4);
                cpa16(kloB + so, klo_g + kbase + r * 52 + c4);
            }
            const long vbase = (long)bh * 104 * 1024 + (k0g >> 1);
            for (int id = tid; id < 104 * 8; id += 256) {
                const int d  = id / 8;
                const int c4 = (id % 8) * 4;
                const uint32_t so = (uint32_t)(d * VTS + c4) * 4;
                cpa16(vhiB + so, vthi_g + vbase + d * 1024 + c4);
                cpa16(vloB + so, vtlo_g + vbase + d * 1024 + c4);
            }
            cpa_commit();
        }
        if (tid < 64) {
            const int t = k0g + tid;
            bias[tid] = alibi[(long)bh * S_LEN + t] * bsc
                      + mask[(long)b_ * S_LEN + t] * LOG2E;
        }
        cpa_wait0();
        __syncthreads();

        // ---- S = Q K^T ----
        float sacc[8][4];
#pragma unroll
        for (int nt = 0; nt < 8; nt++)
#pragma unroll
            for (int r = 0; r < 4; r++) sacc[nt][r] = 0.f;

#pragma unroll
        for (int s = 0; s < 6; s++) {
            unsigned ah[4], al[4];
            ldsm_x4(ah[0], ah[1], ah[2], ah[3], qhiB + q_off0 + s * 32);
            ldsm_x4(al[0], al[1], al[2], al[3], qloB + q_off0 + s * 32);
#pragma unroll
            for (int ntp = 0; ntp < 4; ntp++) {
                const uint32_t koff =
                    (uint32_t)((ntp * 16 + kv_rowoff) * QST + 8 * s + kv_coloff) * 4;
                unsigned bh4[4], bl4[4];
                ldsm_x4(bh4[0], bh4[1], bh4[2], bh4[3], khiB + koff);
                ldsm_x4(bl4[0], bl4[1], bl4[2], bl4[3], kloB + koff);
                mma16(sacc[2 * ntp],     ah, &bh4[0]);
                mma16(sacc[2 * ntp],     ah, &bl4[0]);
                mma16(sacc[2 * ntp],     al, &bh4[0]);
                mma16(sacc[2 * ntp + 1], ah, &bh4[2]);
                mma16(sacc[2 * ntp + 1], ah, &bl4[2]);
                mma16(sacc[2 * ntp + 1], al, &bh4[2]);
            }
        }
        {
            unsigned ah2[2], al2[2];
            const uint32_t qtoff = (uint32_t)((16 * w + gh * 8 + r8) * QST + 48) * 4;
            ldsm_x2(ah2[0], ah2[1], qhiB + qtoff);
            ldsm_x2(al2[0], al2[1], qloB + qtoff);
#pragma unroll
            for (int ntp = 0; ntp < 4; ntp++) {
                const uint32_t ktoff =
                    (uint32_t)((ntp * 16 + gh * 8 + r8) * QST + 48) * 4;
                unsigned kb2[2], kl2[2];
                ldsm_x2(kb2[0], kb2[1], khiB + ktoff);
                ldsm_x2(kl2[0], kl2[1], kloB + ktoff);
                mma8b(sacc[2 * ntp],     ah2, kb2[0]);
                mma8b(sacc[2 * ntp],     ah2, kl2[0]);
                mma8b(sacc[2 * ntp],     al2, kb2[0]);
                mma8b(sacc[2 * ntp + 1], ah2, kb2[1]);
                mma8b(sacc[2 * ntp + 1], ah2, kl2[1]);
                mma8b(sacc[2 * ntp + 1], al2, kb2[1]);
            }
        }

#pragma unroll
        for (int nt = 0; nt < 8; nt++) {
            const int col = nt * 8 + lc * 2;
            const float b0v = bias[col], b1v = bias[col + 1];
            sacc[nt][0] = sacc[nt][0] * sc + b0v;
            sacc[nt][1] = sacc[nt][1] * sc + b1v;
            sacc[nt][2] = sacc[nt][2] * sc + b0v;
            sacc[nt][3] = sacc[nt][3] * sc + b1v;
        }

        // ---- online softmax (log2 domain) ----
        float rm0 = -1e30f, rm1 = -1e30f;
#pragma unroll
        for (int nt = 0; nt < 8; nt++) {
            rm0 = fmaxf(rm0, fmaxf(sacc[nt][0], sacc[nt][1]));
            rm1 = fmaxf(rm1, fmaxf(sacc[nt][2], sacc[nt][3]));
        }
        rm0 = fmaxf(rm0, __shfl_xor_sync(0xffffffffu, rm0, 1));
        rm0 = fmaxf(rm0, __shfl_xor_sync(0xffffffffu, rm0, 2));
        rm1 = fmaxf(rm1, __shfl_xor_sync(0xffffffffu, rm1, 1));
        rm1 = fmaxf(rm1, __shfl_xor_sync(0xffffffffu, rm1, 2));
        const float mn0 = fmaxf(mrow0, rm0);
        const float mn1 = fmaxf(mrow1, rm1);
        const float f0  = exp2f(mrow0 - mn0);
        const float f1  = exp2f(mrow1 - mn1);
        float rs0 = 0.f, rs1 = 0.f;
#pragma unroll
        for (int nt = 0; nt < 8; nt++) {
            sacc[nt][0] = exp2f(sacc[nt][0] - mn0);
            sacc[nt][1] = exp2f(sacc[nt][1] - mn0);
            sacc[nt][2] = exp2f(sacc[nt][2] - mn1);
            sacc[nt][3] = exp2f(sacc[nt][3] - mn1);
            rs0 += sacc[nt][0] + sacc[nt][1];
            rs1 += sacc[nt][2] + sacc[nt][3];
        }
        rs0 += __shfl_xor_sync(0xffffffffu, rs0, 1);
        rs0 += __shfl_xor_sync(0xffffffffu, rs0, 2);
        rs1 += __shfl_xor_sync(0xffffffffu, rs1, 1);
        rs1 += __shfl_xor_sync(0xffffffffu, rs1, 2);
        lsum0 = lsum0 * f0 + rs0;
        lsum1 = lsum1 * f1 + rs1;
        mrow0 = mn0;
        mrow1 = mn1;
#pragma unroll
        for (int nt = 0; nt < NDT; nt++) {
            oacc[nt][0] *= f0; oacc[nt][1] *= f0;
            oacc[nt][2] *= f1; oacc[nt][3] *= f1;
        }

        // ---- pack P to bf16 fragments (registers only) ----
        unsigned aH[8][2], aL[8][2];
#pragma unroll
        for (int nt = 0; nt < 8; nt++) {
            split2(sacc[nt][0], sacc[nt][1], aH[nt][0], aL[nt][0]);
            split2(sacc[nt][2], sacc[nt][3], aH[nt][1], aL[nt][1]);
        }

        // ---- O += P V ----
#pragma unroll
        for (int ks = 0; ks < 4; ks++) {
            unsigned pah[4], pal[4];
            pah[0] = aH[2 * ks][0];     pah[1] = aH[2 * ks][1];
            pah[2] = aH[2 * ks + 1][0]; pah[3] = aH[2 * ks + 1][1];
            pal[0] = aL[2 * ks][0];     pal[1] = aL[2 * ks][1];
            pal[2] = aL[2 * ks + 1][0]; pal[3] = aL[2 * ks + 1][1];
#pragma unroll
            for (int ntp = 0; ntp < 6; ntp++) {
                const uint32_t voff =
                    (uint32_t)((ntp * 16 + kv_rowoff) * VTS + 8 * ks + kv_coloff) * 4;
                unsigned vh4[4], vl4[4];
                ldsm_x4(vh4[0], vh4[1], vh4[2], vh4[3], vhiB + voff);
                ldsm_x4(vl4[0], vl4[1], vl4[2], vl4[3], vloB + voff);
                mma16(oacc[2 * ntp],     pah, &vh4[0]);
                mma16(oacc[2 * ntp],     pah, &vl4[0]);
                mma16(oacc[2 * ntp],     pal, &vh4[0]);
                mma16(oacc[2 * ntp + 1], pah, &vh4[2]);
                mma16(oacc[2 * ntp + 1], pah, &vl4[2]);
                mma16(oacc[2 * ntp + 1], pal, &vh4[2]);
            }
            {
                const uint32_t voff =
                    (uint32_t)((96 + r8) * VTS + 8 * ks + gh * 4) * 4;
                unsigned vh2[2], vl2[2];
                ldsm_x2(vh2[0], vh2[1], vhiB + voff);
                ldsm_x2(vl2[0], vl2[1], vloB + voff);
                mma16(oacc[12], pah, vh2);
                mma16(oacc[12], pah, vl2);
                mma16(oacc[12], pal, vh2);
            }
        }
    }

    // ---- normalize + split-store O into padded (8192, 608 u32) layout ----
    const float il0 = 1.f / lsum0;
    const float il1 = 1.f / lsum1;
    const int r0 = q0 + ar;
#pragma unroll
    for (int nt = 0; nt < NDT; nt++) {
        const int col = nt * 8 + lc * 2;
        if (col < 99) {
            unsigned h, l;
            long F = (long)h_ * (S_LEN * DHEAD) + (long)r0 * DHEAD + col;
            long R = (long)b_ * S_LEN + F / HIDDEN;
            int cu = (int)(F % HIDDEN) >> 1;
            split2(oacc[nt][0] * il0, oacc[nt][1] * il0, h, l);
            ohi_g[R * PU32 + cu] = h; olo_g[R * PU32 + cu] = l;
            F += 8 * DHEAD;
            R = (long)b_ * S_LEN + F / HIDDEN;
            cu = (int)(F % HIDDEN) >> 1;
            split2(oacc[nt][2] * il1, oacc[nt][3] * il1, h, l);
            ohi_g[R * PU32 + cu] = h; olo_g[R * PU32 + cu] = l;
        }
    }
}

// ---------------------------------------------------------------------------
// Launch
// ---------------------------------------------------------------------------
extern "C" void kernel_launch(void* const* d_in, const int* in_sizes, int n_in,
                              void* d_out, int out_size)
{
    const float* x     = (const float*)d_in[0];
    const float* alibi = (const float*)d_in[1];
    const float* mask  = (const float*)d_in[2];
    const float* wq    = (const float*)d_in[3];
    const float* wk    = (const float*)d_in[4];
    const float* wv    = (const float*)d_in[5];
    const float* wo    = (const float*)d_in[6];
    const int*   li    = (const int*)d_in[7];
    float* out = (float*)d_out;

    __nv_bfloat16 *xhi, *xlo, *whi, *wlo;
    unsigned *qhi, *qlo, *khi, *klo, *vthi, *vtlo, *ohi, *olo;
    cudaGetSymbolAddress((void**)&xhi, g_xhi);
    cudaGetSymbolAddress((void**)&xlo, g_xlo);
    cudaGetSymbolAddress((void**)&whi, g_whi);
    cudaGetSymbolAddress((void**)&wlo, g_wlo);
    cudaGetSymbolAddress((void**)&qhi, g_qhi);
    cudaGetSymbolAddress((void**)&qlo, g_qlo);
    cudaGetSymbolAddress((void**)&khi, g_khi);
    cudaGetSymbolAddress((void**)&klo, g_klo);
    cudaGetSymbolAddress((void**)&vthi, g_vthi);
    cudaGetSymbolAddress((void**)&vtlo, g_vtlo);
    cudaGetSymbolAddress((void**)&ohi, g_ohi);
    cudaGetSymbolAddress((void**)&olo, g_olo);

    cudaFuncSetAttribute(flash_kernel,
                         cudaFuncAttributeMaxDynamicSharedMemorySize, FL_SMEM_BYTES);
    cudaFuncSetAttribute(gemm_qkv_kernel,
                         cudaFuncAttributeMaxDynamicSharedMemorySize, GT_SMEM);
    cudaFuncSetAttribute(gemm_o_kernel,
                         cudaFuncAttributeMaxDynamicSharedMemorySize, GT_SMEM);

    // prep: pads + out zeroing (for atomic split-K) + fused split
    const long totZero = (long)M_TOT * HIDDEN;       // largest init range
    init_pads_kernel<<<(int)((totZero + 255) / 256), 256>>>(
        qhi, qlo, khi, klo, vthi, vtlo, ohi, olo, out);
    const long totAll = (long)M_TOT * PCOLS + 4L * PROWSW * PCOLS;
    split_all_kernel<<<(int)((totAll + 255) / 256), 256>>>(
        x, wq, wk, wv, wo, xhi, xlo, whi, wlo);

    const long totW = (long)PROWSW * PCOLS;
    gemm_qkv_kernel<<<dim3(M_TOT / 128, PROWSW / 128, 3), 256, GT_SMEM>>>(
        xhi, xlo, whi, wlo, qhi, qlo, khi, klo, vthi, vtlo);

    flash_kernel<<<dim3(BH, S_LEN / 128), 256, FL_SMEM_BYTES>>>(
        alibi, mask, li, qhi, qlo, khi, klo, vthi, vtlo, ohi, olo);

    gemm_o_kernel<<<dim3(M_TOT / 128, PROWSW / 128, 2), 256, GT_SMEM>>>(
        ohi, olo, whi + 3L * totW, wlo + 3L * totW, out);
}

// round 17
// speedup vs baseline: 1.0203x; 1.0203x over previous
#include <cuda_runtime.h>
#include <cuda_bf16.h>
#include <cstdint>
#include <math.h>

// Problem constants
#define BATCH  4
#define S_LEN  2048
#define NHEAD  12
#define DHEAD  100
#define HIDDEN 1200
#define M_TOT  (BATCH * S_LEN)          // 8192
#define BH     (BATCH * NHEAD)          // 48
#define PCOLS  1216                     // K padded (19*64)
#define PU32   608                      // PCOLS/2 in u32
#define PROWSW 1280                     // weight rows padded

// ---------------------------------------------------------------------------
// Scratch (pre-split bf16 hi/lo, SEPARATE arrays — known-good layout)
// ---------------------------------------------------------------------------
__device__ __align__(16) __nv_bfloat16 g_xhi[M_TOT * PCOLS];
__device__ __align__(16) __nv_bfloat16 g_xlo[M_TOT * PCOLS];
__device__ __align__(16) __nv_bfloat16 g_whi[4][PROWSW * PCOLS];
__device__ __align__(16) __nv_bfloat16 g_wlo[4][PROWSW * PCOLS];
// Q,K: (bh, s, 52 u32) packed bf16 pairs along d (pads 50,51 zero)
__device__ __align__(16) unsigned g_qhi[BH * S_LEN * 52];
__device__ __align__(16) unsigned g_qlo[BH * S_LEN * 52];
__device__ __align__(16) unsigned g_khi[BH * S_LEN * 52];
__device__ __align__(16) unsigned g_klo[BH * S_LEN * 52];
// V^T: (bh, 104 d-rows, 1024 u32) packed pairs along s (d rows 100..103 zero)
__device__ __align__(16) unsigned g_vthi[BH * 104 * 1024];
__device__ __align__(16) unsigned g_vtlo[BH * 104 * 1024];
// O: padded (8192, 608 u32) packed pairs (cols 600..607 zero)
__device__ __align__(16) unsigned g_ohi[M_TOT * PU32];
__device__ __align__(16) unsigned g_olo[M_TOT * PU32];

// ---------------------------------------------------------------------------
// BF16 helpers + mma.sync + ldmatrix + cp.async
// ---------------------------------------------------------------------------
__device__ __forceinline__ unsigned cvt2(float even, float odd) {
    unsigned r;
    asm("cvt.rn.bf16x2.f32 %0, %1, %2;" : "=r"(r) : "f"(odd), "f"(even));
    return r;
}
__device__ __forceinline__ float bf_lo(unsigned p) { return __uint_as_float(p << 16); }
__device__ __forceinline__ float bf_hi(unsigned p) { return __uint_as_float(p & 0xFFFF0000u); }
__device__ __forceinline__ void split2(float e, float o, unsigned& h, unsigned& l) {
    h = cvt2(e, o);
    l = cvt2(e - bf_lo(h), o - bf_hi(h));
}
__device__ __forceinline__ void mma16(float* c, const unsigned* a, const unsigned* b) {
    asm volatile(
        "mma.sync.aligned.m16n8k16.row.col.f32.bf16.bf16.f32 "
        "{%0,%1,%2,%3}, {%4,%5,%6,%7}, {%8,%9}, {%0,%1,%2,%3};\n"
        : "+f"(c[0]), "+f"(c[1]), "+f"(c[2]), "+f"(c[3])
        : "r"(a[0]), "r"(a[1]), "r"(a[2]), "r"(a[3]), "r"(b[0]), "r"(b[1]));
}
__device__ __forceinline__ void mma8b(float* c, const unsigned* a, unsigned b) {
    asm volatile(
        "mma.sync.aligned.m16n8k8.row.col.f32.bf16.bf16.f32 "
        "{%0,%1,%2,%3}, {%4,%5}, {%6}, {%0,%1,%2,%3};\n"
        : "+f"(c[0]), "+f"(c[1]), "+f"(c[2]), "+f"(c[3])
        : "r"(a[0]), "r"(a[1]), "r"(b));
}
__device__ __forceinline__ void ldsm_x4(unsigned& r0, unsigned& r1, unsigned& r2,
                                        unsigned& r3, uint32_t a) {
    asm volatile("ldmatrix.sync.aligned.m8n8.x4.shared.b16 {%0,%1,%2,%3}, [%4];"
                 : "=r"(r0), "=r"(r1), "=r"(r2), "=r"(r3) : "r"(a));
}
__device__ __forceinline__ void ldsm_x2(unsigned& r0, unsigned& r1, uint32_t a) {
    asm volatile("ldmatrix.sync.aligned.m8n8.x2.shared.b16 {%0,%1}, [%2];"
                 : "=r"(r0), "=r"(r1) : "r"(a));
}
__device__ __forceinline__ void cpa16(uint32_t s_addr, const void* g) {
    asm volatile("cp.async.cg.shared.global [%0], [%1], 16;" :: "r"(s_addr), "l"(g));
}
__device__ __forceinline__ void cpa_commit() {
    asm volatile("cp.async.commit_group;");
}
__device__ __forceinline__ void cpa_wait0() {
    asm volatile("cp.async.wait_group 0;");
}
__device__ __forceinline__ uint32_t smem_u32p(const void* p) {
    uint32_t a;
    asm("{ .reg .u64 t; cvta.to.shared.u64 t, %1; cvt.u32.u64 %0, t; }" : "=r"(a) : "l"(p));
    return a;
}

// ---------------------------------------------------------------------------
// Prep: fp32 -> bf16 hi/lo for x AND all 4 weights in ONE launch.
// ---------------------------------------------------------------------------
__global__ void split_all_kernel(const float* __restrict__ x,
                                 const float* __restrict__ w0, const float* __restrict__ w1,
                                 const float* __restrict__ w2, const float* __restrict__ w3,
                                 __nv_bfloat16* __restrict__ xhi, __nv_bfloat16* __restrict__ xlo,
                                 __nv_bfloat16* __restrict__ whi, __nv_bfloat16* __restrict__ wlo)
{
    const long totX = (long)M_TOT * PCOLS;
    const long totW = (long)PROWSW * PCOLS;
    const long i = (long)blockIdx.x * 256 + threadIdx.x;
    if (i >= totX + 4 * totW) return;

    const float* src;
    __nv_bfloat16 *dhi, *dlo;
    int rows;
    long j;
    if (i < totX) {
        src = x; dhi = xhi; dlo = xlo; rows = M_TOT; j = i;
    } else {
        const long t = i - totX;
        const int wsel = (int)(t / totW);
        j = t - (long)wsel * totW;
        src = (wsel == 0) ? w0 : (wsel == 1) ? w1 : (wsel == 2) ? w2 : w3;
        dhi = whi + (long)wsel * totW;
        dlo = wlo + (long)wsel * totW;
        rows = HIDDEN;
    }
    const int r = (int)(j / PCOLS);
    const int c = (int)(j - (long)r * PCOLS);
    float v = (r < rows && c < HIDDEN) ? src[(long)r * HIDDEN + c] : 0.f;
    __nv_bfloat16 h = __float2bfloat16(v);
    dhi[j] = h;
    dlo[j] = __float2bfloat16(v - __bfloat162float(h));
}

// Zero pad regions: Q/K u32 cols 50,51; Vt d-rows 100..103; O u32 cols 600..607
__global__ void init_pads_kernel(unsigned* qhi, unsigned* qlo, unsigned* khi, unsigned* klo,
                                 unsigned* vthi, unsigned* vtlo, unsigned* ohi, unsigned* olo)
{
    const int i = blockIdx.x * 256 + threadIdx.x;
    if (i < BH * S_LEN * 2) {
        const int r = i >> 1;
        const long a = (long)r * 52 + 50 + (i & 1);
        qhi[a] = 0u; qlo[a] = 0u; khi[a] = 0u; klo[a] = 0u;
    }
    if (i < BH * 4 * 1024) {
        const int bh = i >> 12;
        const long a = ((long)bh * 104 + 100) * 1024 + (i & 4095);
        vthi[a] = 0u; vtlo[a] = 0u;
    }
    if (i < M_TOT * 8) {
        const long a = (long)(i >> 3) * PU32 + 600 + (i & 7);
        ohi[a] = 0u; olo[a] = 0u;
    }
}

// ---------------------------------------------------------------------------
// GEMM core (R15 verbatim — known-good): C[m,n] = sum_k A[m,k]*W[n,k].
// 128x128 tile, BK=64, 19 chunks, 256 threads, warp tile 64x32, 2 CTAs/SM.
// smem u32 arrays [128][36]: AHI ALO BHI BLO.  cp.async + immediate wait.
// mode 0: f32 row-major (M,1200);  mode 1: Q/K hi-lo layout;  mode 3: V^T.
// ---------------------------------------------------------------------------
#define GS_ALO 18432
#define GS_BHI 36864
#define GS_BLO 55296
#define GT_SMEM 73728

__device__ __forceinline__ void gemm_core(
    unsigned char* smb,
    const unsigned* __restrict__ Ahi_u, const unsigned* __restrict__ Alo_u,
    const unsigned* __restrict__ Bhi_u, const unsigned* __restrict__ Blo_u,
    float* __restrict__ Cf, unsigned* __restrict__ Chi, unsigned* __restrict__ Clo,
    int mode, int m0, int n0)
{
    unsigned* AHI = (unsigned*)smb;
    unsigned* ALO = (unsigned*)(smb + GS_ALO);
    unsigned* BHI = (unsigned*)(smb + GS_BHI);
    unsigned* BLO = (unsigned*)(smb + GS_BLO);
    const uint32_t sb = smem_u32p(smb);

    const int tid  = threadIdx.x;
    const int lane = tid & 31;
    const int warp = tid >> 5;
    const int wm   = warp >> 2;     // 0..1
    const int wn   = warp & 3;      // 0..3
    const int lr   = lane >> 2;
    const int lc   = lane & 3;

    float acc[4][4][4];
#pragma unroll
    for (int i = 0; i < 4; i++)
#pragma unroll
        for (int j = 0; j < 4; j++)
#pragma unroll
            for (int r = 0; r < 4; r++) acc[i][j][r] = 0.f;

    const int lrow = tid >> 3;        // 0..31
    const int cn   = tid & 7;         // 16B chunk

    for (int ch = 0; ch < PCOLS / 64; ch++) {
        __syncthreads();
#pragma unroll
        for (int q = 0; q < 4; q++) {
            const int row = lrow + q * 32;
            const long a_off = (long)(m0 + row) * PU32 + ch * 32 + cn * 4;
            const long b_off = (long)(n0 + row) * PU32 + ch * 32 + cn * 4;
            const uint32_t so = (uint32_t)(row * 36 + cn * 4) * 4;
            cpa16(sb + so,          Ahi_u + a_off);
            cpa16(sb + GS_ALO + so, Alo_u + a_off);
            cpa16(sb + GS_BHI + so, Bhi_u + b_off);
            cpa16(sb + GS_BLO + so, Blo_u + b_off);
        }
        cpa_commit();
        cpa_wait0();
        __syncthreads();

#pragma unroll
        for (int s = 0; s < 4; s++) {
            unsigned bhv[4][2], blv[4][2];
#pragma unroll
            for (int nt = 0; nt < 4; nt++) {
                const int n = wn * 32 + nt * 8 + lr;
                bhv[nt][0] = BHI[n * 36 + 8 * s + lc];
                bhv[nt][1] = BHI[n * 36 + 8 * s + 4 + lc];
                blv[nt][0] = BLO[n * 36 + 8 * s + lc];
                blv[nt][1] = BLO[n * 36 + 8 * s + 4 + lc];
            }
#pragma unroll
            for (int mt = 0; mt < 4; mt++) {
                const int m = wm * 64 + mt * 16 + lr;
                unsigned ah[4], al[4];
                ah[0] = AHI[m * 36 + 8 * s + lc];       ah[1] = AHI[(m + 8) * 36 + 8 * s + lc];
                ah[2] = AHI[m * 36 + 8 * s + 4 + lc];   ah[3] = AHI[(m + 8) * 36 + 8 * s + 4 + lc];
                al[0] = ALO[m * 36 + 8 * s + lc];       al[1] = ALO[(m + 8) * 36 + 8 * s + lc];
                al[2] = ALO[m * 36 + 8 * s + 4 + lc];   al[3] = ALO[(m + 8) * 36 + 8 * s + 4 + lc];
                // interleaved over nt: consecutive mmas hit different accumulators
#pragma unroll
                for (int nt = 0; nt < 4; nt++) mma16(acc[mt][nt], ah, bhv[nt]);
#pragma unroll
                for (int nt = 0; nt < 4; nt++) mma16(acc[mt][nt], ah, blv[nt]);
#pragma unroll
                for (int nt = 0; nt < 4; nt++) mma16(acc[mt][nt], al, bhv[nt]);
            }
        }
    }

    // ---- Epilogue ----
    if (mode == 3) {
        __syncthreads();
        float* Ct = (float*)smb;   // [128 n][129 m]
#pragma unroll
        for (int mt = 0; mt < 4; mt++)
#pragma unroll
            for (int nt = 0; nt < 4; nt++) {
                const int mL = wm * 64 + mt * 16 + lr;
                const int nL = wn * 32 + nt * 8 + lc * 2;
                Ct[(nL)     * 129 + mL]     = acc[mt][nt][0];
                Ct[(nL + 1) * 129 + mL]     = acc[mt][nt][1];
                Ct[(nL)     * 129 + mL + 8] = acc[mt][nt][2];
                Ct[(nL + 1) * 129 + mL + 8] = acc[mt][nt][3];
            }
        __syncthreads();
#pragma unroll
        for (int it = 0; it < 32; it++) {
            const int idx = tid + it * 256;    // 0..8191
            const int nL  = idx >> 6;          // 0..127
            const int mp  = idx & 63;          // m-pair
            const int n   = n0 + nL;
            if (n < HIDDEN) {
                const float c0 = Ct[nL * 129 + 2 * mp];
                const float c1 = Ct[nL * 129 + 2 * mp + 1];
                const int m = m0 + 2 * mp;
                const int b_ = m >> 11, s_ = m & (S_LEN - 1);
                const int h_ = n / DHEAD, d_ = n % DHEAD;
                unsigned h, l;
                split2(c0, c1, h, l);
                const long a = ((long)(b_ * NHEAD + h_) * 104 + d_) * 1024 + (s_ >> 1);
                Chi[a] = h; Clo[a] = l;
            }
        }
        return;
    }

#pragma unroll
    for (int mt = 0; mt < 4; mt++) {
#pragma unroll
        for (int nt = 0; nt < 4; nt++) {
            const int nn = n0 + wn * 32 + nt * 8 + lc * 2;
            if (nn >= HIDDEN) continue;
#pragma unroll
            for (int half = 0; half < 2; half++) {
                const int mm = m0 + wm * 64 + mt * 16 + lr + half * 8;
                const float c0 = acc[mt][nt][half * 2];
                const float c1 = acc[mt][nt][half * 2 + 1];
                if (mode == 0) {
                    *(float2*)&Cf[(long)mm * HIDDEN + nn] = make_float2(c0, c1);
                } else {
                    const int b_ = mm >> 11, s_ = mm & (S_LEN - 1);
                    const int h_ = nn / DHEAD, d_ = nn % DHEAD;
                    unsigned h, l;
                    split2(c0, c1, h, l);
                    const long a = ((long)(b_ * NHEAD + h_) * S_LEN + s_) * 52 + (d_ >> 1);
                    Chi[a] = h; Clo[a] = l;
                }
            }
        }
    }
}

// Fused QKV: grid.z selects weight + destination + mode.
__global__ __launch_bounds__(256, 2) void gemm_qkv_kernel(
    const __nv_bfloat16* __restrict__ xhi, const __nv_bfloat16* __restrict__ xlo,
    const __nv_bfloat16* __restrict__ whi, const __nv_bfloat16* __restrict__ wlo,
    unsigned* __restrict__ qhi, unsigned* __restrict__ qlo,
    unsigned* __restrict__ khi, unsigned* __restrict__ klo,
    unsigned* __restrict__ vthi, unsigned* __restrict__ vtlo)
{
    extern __shared__ unsigned char smb[];
    const int z = blockIdx.z;
    const long wo = (long)z * PROWSW * PCOLS;
    unsigned* Chi = (z == 0) ? qhi : (z == 1) ? khi : vthi;
    unsigned* Clo = (z == 0) ? qlo : (z == 1) ? klo : vtlo;
    const int mode = (z == 2) ? 3 : 1;
    gemm_core(smb,
              (const unsigned*)xhi, (const unsigned*)xlo,
              (const unsigned*)(whi + wo), (const unsigned*)(wlo + wo),
              nullptr, Chi, Clo, mode,
              blockIdx.x * 128, blockIdx.y * 128);
}

// Output projection: O (pre-split) @ Wo^T -> f32 out.
__global__ __launch_bounds__(256, 2) void gemm_o_kernel(
    const unsigned* __restrict__ ohi, const unsigned* __restrict__ olo,
    const __nv_bfloat16* __restrict__ whi, const __nv_bfloat16* __restrict__ wlo,
    float* __restrict__ out)
{
    extern __shared__ unsigned char smb[];
    gemm_core(smb, ohi, olo,
              (const unsigned*)whi, (const unsigned*)wlo,
              out, nullptr, nullptr, 0,
              blockIdx.x * 128, blockIdx.y * 128);
}

// ---------------------------------------------------------------------------
// Flash attention (R15 + interleaved mma issue). 256 threads, q-tile 128,
// kv 64, exp2-domain softmax.
// ---------------------------------------------------------------------------
#define QST 52
#define VTS 36
#define QHI_OFF  0
#define QLO_OFF  6656
#define KHI_OFF  13312
#define KLO_OFF  16640
#define VTHI_OFF 19968
#define VTLO_OFF 23712
#define BIAS_OFF 27456
#define FL_SMEM_U32 27520
#define FL_SMEM_BYTES (FL_SMEM_U32 * 4)
#define NDT 13

__global__ __launch_bounds__(256, 2) void flash_kernel(
    const float* __restrict__ alibi, const float* __restrict__ mask,
    const int* __restrict__ layer_index,
    const unsigned* __restrict__ qhi_g, const unsigned* __restrict__ qlo_g,
    const unsigned* __restrict__ khi_g, const unsigned* __restrict__ klo_g,
    const unsigned* __restrict__ vthi_g, const unsigned* __restrict__ vtlo_g,
    unsigned* __restrict__ ohi_g, unsigned* __restrict__ olo_g)
{
    extern __shared__ unsigned smu[];
    unsigned* Qhi  = smu + QHI_OFF;
    unsigned* Qlo  = smu + QLO_OFF;
    float*    bias = (float*)(smu + BIAS_OFF);

    const int tid  = threadIdx.x;
    const int lane = tid & 31;
    const int w    = tid >> 5;
    const int lr   = lane >> 2;
    const int lc   = lane & 3;
    const int bh   = blockIdx.x;
    const int q0   = blockIdx.y * 128;
    const int b_   = bh / NHEAD;
    const int h_   = bh % NHEAD;

    const float LOG2E = 1.4426950408889634f;
    const float inv = 1.f / (float)(layer_index[0] + 1);
    const float sc  = 10.f * inv * LOG2E;
    const float bsc = inv * LOG2E;

    const int g8 = lane >> 3;
    const int r8 = lane & 7;
    const int gh = (lane >> 3) & 1;

    const uint32_t qhiB = smem_u32p(smu + QHI_OFF), qloB = smem_u32p(smu + QLO_OFF);
    const uint32_t khiB = smem_u32p(smu + KHI_OFF), kloB = smem_u32p(smu + KLO_OFF);
    const uint32_t vhiB = smem_u32p(smu + VTHI_OFF), vloB = smem_u32p(smu + VTLO_OFF);

    const int q_row = 16 * w + ((g8 & 1) << 3) + r8;
    const uint32_t q_off0 = (uint32_t)(q_row * QST + ((g8 >> 1) << 2)) * 4;
    const int kv_rowoff = ((g8 >> 1) << 3) + r8;
    const int kv_coloff = (g8 & 1) << 2;

    {
        const long qbase = ((long)bh * S_LEN + q0) * 52;
        for (int id = tid; id < 128 * 13; id += 256) {
            const int r  = id / 13;
            const int c4 = (id % 13) * 4;
            *(uint4*)&Qhi[r * QST + c4] = *(const uint4*)&qhi_g[qbase + r * 52 + c4];
            *(uint4*)&Qlo[r * QST + c4] = *(const uint4*)&qlo_g[qbase + r * 52 + c4];
        }
    }

    float oacc[NDT][4];
#pragma unroll
    for (int nt = 0; nt < NDT; nt++)
#pragma unroll
        for (int r = 0; r < 4; r++) oacc[nt][r] = 0.f;
    float mrow0 = -1e30f, mrow1 = -1e30f, lsum0 = 0.f, lsum1 = 0.f;

    const int ar = 16 * w + lr;

    for (int kt = 0; kt < S_LEN / 64; kt++) {
        const int k0g = kt * 64;
        __syncthreads();

        {
            const long kbase = ((long)bh * S_LEN + k0g) * 52;
            for (int id = tid; id < 64 * 13; id += 256) {
                const int r  = id / 13;
                const int c4 = (id % 13) * 4;
                const uint32_t so = (uint32_t)(r * QST + c4) * 4;
                cpa16(khiB + so, khi_g + kbase + r * 52 + c4);
                cpa16(kloB + so, klo_g + kbase + r * 52 + c4);
            }
            const long vbase = (long)bh * 104 * 1024 + (k0g >> 1);
            for (int id = tid; id < 104 * 8; id += 256) {
                const int d  = id / 8;
                const int c4 = (id % 8) * 4;
                const uint32_t so = (uint32_t)(d * VTS + c4) * 4;
                cpa16(vhiB + so, vthi_g + vbase + d * 1024 + c4);
                cpa16(vloB + so, vtlo_g + vbase + d * 1024 + c4);
            }
            cpa_commit();
        }
        if (tid < 64) {
            const int t = k0g + tid;
            bias[tid] = alibi[(long)bh * S_LEN + t] * bsc
                      + mask[(long)b_ * S_LEN + t] * LOG2E;
        }
        cpa_wait0();
        __syncthreads();

        // ---- S = Q K^T ----
        float sacc[8][4];
#pragma unroll
        for (int nt = 0; nt < 8; nt++)
#pragma unroll
            for (int r = 0; r < 4; r++) sacc[nt][r] = 0.f;

#pragma unroll
        for (int s = 0; s < 6; s++) {
            unsigned ah[4], al[4];
            ldsm_x4(ah[0], ah[1], ah[2], ah[3], qhiB + q_off0 + s * 32);
            ldsm_x4(al[0], al[1], al[2], al[3], qloB + q_off0 + s * 32);
#pragma unroll
            for (int ntp = 0; ntp < 4; ntp++) {
                const uint32_t koff =
                    (uint32_t)((ntp * 16 + kv_rowoff) * QST + 8 * s + kv_coloff) * 4;
                unsigned bh4[4], bl4[4];
                ldsm_x4(bh4[0], bh4[1], bh4[2], bh4[3], khiB + koff);
                ldsm_x4(bl4[0], bl4[1], bl4[2], bl4[3], kloB + koff);
                // interleaved: consecutive mmas target different accumulators
                mma16(sacc[2 * ntp],     ah, &bh4[0]);
                mma16(sacc[2 * ntp + 1], ah, &bh4[2]);
                mma16(sacc[2 * ntp],     ah, &bl4[0]);
                mma16(sacc[2 * ntp + 1], ah, &bl4[2]);
                mma16(sacc[2 * ntp],     al, &bh4[0]);
                mma16(sacc[2 * ntp + 1], al, &bh4[2]);
            }
        }
        {
            unsigned ah2[2], al2[2];
            const uint32_t qtoff = (uint32_t)((16 * w + gh * 8 + r8) * QST + 48) * 4;
            ldsm_x2(ah2[0], ah2[1], qhiB + qtoff);
            ldsm_x2(al2[0], al2[1], qloB + qtoff);
#pragma unroll
            for (int ntp = 0; ntp < 4; ntp++) {
                const uint32_t ktoff =
                    (uint32_t)((ntp * 16 + gh * 8 + r8) * QST + 48) * 4;
                unsigned kb2[2], kl2[2];
                ldsm_x2(kb2[0], kb2[1], khiB + ktoff);
                ldsm_x2(kl2[0], kl2[1], kloB + ktoff);
                mma8b(sacc[2 * ntp],     ah2, kb2[0]);
                mma8b(sacc[2 * ntp + 1], ah2, kb2[1]);
                mma8b(sacc[2 * ntp],     ah2, kl2[0]);
                mma8b(sacc[2 * ntp + 1], ah2, kl2[1]);
                mma8b(sacc[2 * ntp],     al2, kb2[0]);
                mma8b(sacc[2 * ntp + 1], al2, kb2[1]);
            }
        }

#pragma unroll
        for (int nt = 0; nt < 8; nt++) {
            const int col = nt * 8 + lc * 2;
            const float b0v = bias[col], b1v = bias[col + 1];
            sacc[nt][0] = sacc[nt][0] * sc + b0v;
            sacc[nt][1] = sacc[nt][1] * sc + b1v;
            sacc[nt][2] = sacc[nt][2] * sc + b0v;
            sacc[nt][3] = sacc[nt][3] * sc + b1v;
        }

        // ---- online softmax (log2 domain) ----
        float rm0 = -1e30f, rm1 = -1e30f;
#pragma unroll
        for (int nt = 0; nt < 8; nt++) {
            rm0 = fmaxf(rm0, fmaxf(sacc[nt][0], sacc[nt][1]));
            rm1 = fmaxf(rm1, fmaxf(sacc[nt][2], sacc[nt][3]));
        }
        rm0 = fmaxf(rm0, __shfl_xor_sync(0xffffffffu, rm0, 1));
        rm0 = fmaxf(rm0, __shfl_xor_sync(0xffffffffu, rm0, 2));
        rm1 = fmaxf(rm1, __shfl_xor_sync(0xffffffffu, rm1, 1));
        rm1 = fmaxf(rm1, __shfl_xor_sync(0xffffffffu, rm1, 2));
        const float mn0 = fmaxf(mrow0, rm0);
        const float mn1 = fmaxf(mrow1, rm1);
        const float f0  = exp2f(mrow0 - mn0);
        const float f1  = exp2f(mrow1 - mn1);
        float rs0 = 0.f, rs1 = 0.f;
#pragma unroll
        for (int nt = 0; nt < 8; nt++) {
            sacc[nt][0] = exp2f(sacc[nt][0] - mn0);
            sacc[nt][1] = exp2f(sacc[nt][1] - mn0);
            sacc[nt][2] = exp2f(sacc[nt][2] - mn1);
            sacc[nt][3] = exp2f(sacc[nt][3] - mn1);
            rs0 += sacc[nt][0] + sacc[nt][1];
            rs1 += sacc[nt][2] + sacc[nt][3];
        }
        rs0 += __shfl_xor_sync(0xffffffffu, rs0, 1);
        rs0 += __shfl_xor_sync(0xffffffffu, rs0, 2);
        rs1 += __shfl_xor_sync(0xffffffffu, rs1, 1);
        rs1 += __shfl_xor_sync(0xffffffffu, rs1, 2);
        lsum0 = lsum0 * f0 + rs0;
        lsum1 = lsum1 * f1 + rs1;
        mrow0 = mn0;
        mrow1 = mn1;
#pragma unroll
        for (int nt = 0; nt < NDT; nt++) {
            oacc[nt][0] *= f0; oacc[nt][1] *= f0;
            oacc[nt][2] *= f1; oacc[nt][3] *= f1;
        }

        // ---- pack P to bf16 fragments (registers only) ----
        unsigned aH[8][2], aL[8][2];
#pragma unroll
        for (int nt = 0; nt < 8; nt++) {
            split2(sacc[nt][0], sacc[nt][1], aH[nt][0], aL[nt][0]);
            split2(sacc[nt][2], sacc[nt][3], aH[nt][1], aL[nt][1]);
        }

        // ---- O += P V ----
#pragma unroll
        for (int ks = 0; ks < 4; ks++) {
            unsigned pah[4], pal[4];
            pah[0] = aH[2 * ks][0];     pah[1] = aH[2 * ks][1];
            pah[2] = aH[2 * ks + 1][0]; pah[3] = aH[2 * ks + 1][1];
            pal[0] = aL[2 * ks][0];     pal[1] = aL[2 * ks][1];
            pal[2] = aL[2 * ks + 1][0]; pal[3] = aL[2 * ks + 1][1];
#pragma unroll
            for (int ntp = 0; ntp < 6; ntp++) {
                const uint32_t voff =
                    (uint32_t)((ntp * 16 + kv_rowoff) * VTS + 8 * ks + kv_coloff) * 4;
                unsigned vh4[4], vl4[4];
                ldsm_x4(vh4[0], vh4[1], vh4[2], vh4[3], vhiB + voff);
                ldsm_x4(vl4[0], vl4[1], vl4[2], vl4[3], vloB + voff);
                // interleaved over the accumulator pair
                mma16(oacc[2 * ntp],     pah, &vh4[0]);
                mma16(oacc[2 * ntp + 1], pah, &vh4[2]);
                mma16(oacc[2 * ntp],     pah, &vl4[0]);
                mma16(oacc[2 * ntp + 1], pah, &vl4[2]);
                mma16(oacc[2 * ntp],     pal, &vh4[0]);
                mma16(oacc[2 * ntp + 1], pal, &vh4[2]);
            }
            {
                const uint32_t voff =
                    (uint32_t)((96 + r8) * VTS + 8 * ks + gh * 4) * 4;
                unsigned vh2[2], vl2[2];
                ldsm_x2(vh2[0], vh2[1], vhiB + voff);
                ldsm_x2(vl2[0], vl2[1], vloB + voff);
                mma16(oacc[12], pah, vh2);
                mma16(oacc[12], pah, vl2);
                mma16(oacc[12], pal, vh2);
            }
        }
    }

    // ---- normalize + split-store O into padded (8192, 608 u32) layout ----
    const float il0 = 1.f / lsum0;
    const float il1 = 1.f / lsum1;
    const int r0 = q0 + ar;
#pragma unroll
    for (int nt = 0; nt < NDT; nt++) {
        const int col = nt * 8 + lc * 2;
        if (col < 99) {
            unsigned h, l;
            long F = (long)h_ * (S_LEN * DHEAD) + (long)r0 * DHEAD + col;
            long R = (long)b_ * S_LEN + F / HIDDEN;
            int cu = (int)(F % HIDDEN) >> 1;
            split2(oacc[nt][0] * il0, oacc[nt][1] * il0, h, l);
            ohi_g[R * PU32 + cu] = h; olo_g[R * PU32 + cu] = l;
            F += 8 * DHEAD;
            R = (long)b_ * S_LEN + F / HIDDEN;
            cu = (int)(F % HIDDEN) >> 1;
            split2(oacc[nt][2] * il1, oacc[nt][3] * il1, h, l);
            ohi_g[R * PU32 + cu] = h; olo_g[R * PU32 + cu] = l;
        }
    }
}

// ---------------------------------------------------------------------------
// Launch
// ---------------------------------------------------------------------------
extern "C" void kernel_launch(void* const* d_in, const int* in_sizes, int n_in,
                              void* d_out, int out_size)
{
    const float* x     = (const float*)d_in[0];
    const float* alibi = (const float*)d_in[1];
    const float* mask  = (const float*)d_in[2];
    const float* wq    = (const float*)d_in[3];
    const float* wk    = (const float*)d_in[4];
    const float* wv    = (const float*)d_in[5];
    const float* wo    = (const float*)d_in[6];
    const int*   li    = (const int*)d_in[7];
    float* out = (float*)d_out;

    __nv_bfloat16 *xhi, *xlo, *whi, *wlo;
    unsigned *qhi, *qlo, *khi, *klo, *vthi, *vtlo, *ohi, *olo;
    cudaGetSymbolAddress((void**)&xhi, g_xhi);
    cudaGetSymbolAddress((void**)&xlo, g_xlo);
    cudaGetSymbolAddress((void**)&whi, g_whi);
    cudaGetSymbolAddress((void**)&wlo, g_wlo);
    cudaGetSymbolAddress((void**)&qhi, g_qhi);
    cudaGetSymbolAddress((void**)&qlo, g_qlo);
    cudaGetSymbolAddress((void**)&khi, g_khi);
    cudaGetSymbolAddress((void**)&klo, g_klo);
    cudaGetSymbolAddress((void**)&vthi, g_vthi);
    cudaGetSymbolAddress((void**)&vtlo, g_vtlo);
    cudaGetSymbolAddress((void**)&ohi, g_ohi);
    cudaGetSymbolAddress((void**)&olo, g_olo);

    cudaFuncSetAttribute(flash_kernel,
                         cudaFuncAttributeMaxDynamicSharedMemorySize, FL_SMEM_BYTES);
    cudaFuncSetAttribute(gemm_qkv_kernel,
                         cudaFuncAttributeMaxDynamicSharedMemorySize, GT_SMEM);
    cudaFuncSetAttribute(gemm_o_kernel,
                         cudaFuncAttributeMaxDynamicSharedMemorySize, GT_SMEM);

    // prep: pads + one fused split over x and all 4 weights
    init_pads_kernel<<<768, 256>>>(qhi, qlo, khi, klo, vthi, vtlo, ohi, olo);
    const long totAll = (long)M_TOT * PCOLS + 4L * PROWSW * PCOLS;
    split_all_kernel<<<(int)((totAll + 255) / 256), 256>>>(
        x, wq, wk, wv, wo, xhi, xlo, whi, wlo);

    const long totW = (long)PROWSW * PCOLS;
    gemm_qkv_kernel<<<dim3(M_TOT / 128, PROWSW / 128, 3), 256, GT_SMEM>>>(
        xhi, xlo, whi, wlo, qhi, qlo, khi, klo, vthi, vtlo);

    flash_kernel<<<dim3(BH, S_LEN / 128), 256, FL_SMEM_BYTES>>>(
        alibi, mask, li, qhi, qlo, khi, klo, vthi, vtlo, ohi, olo);

    gemm_o_kernel<<<dim3(M_TOT / 128, PROWSW / 128), 256, GT_SMEM>>>(
        ohi, olo, whi + 3L * totW, wlo + 3L * totW, out);
}